// round 11
// baseline (speedup 1.0000x reference)
#include <cuda_runtime.h>
#include <cuda_fp16.h>
#include <stdint.h>

// Problem constants (fixed shapes)
#define BATCH 8
#define HH 1024
#define WW 1024
#define HW (HH * WW)

#define TILE 32
#define NTHREADS 256

#define HALO_Y 7            // search radius 5 + patch radius 2
#define HALO_RGB 5
#define SY_DIM 46           // 32 + 2*7
#define SY_STRIDE 48
#define SRGB_DIM 42         // 32 + 2*5
#define SRGB_STRIDE 45      // odd -> conflict-free for stage-C pattern
#define CS_COLS 36          // columns j in [-2, 34)
#define CS_STRIDE 40        // multiple of 4 -> LDS.128-able in stage C

#define N_SY (SY_DIM * SY_DIM)
#define N_SRGB (SRGB_DIM * SRGB_DIM)
#define N_CS_TASKS 252      // 7 vertical runs x 36 columns

// w = exp(-sqrt(S)/(h+1e-6)) = exp2(-sqrt(c^2 * S)), c = log2(e)/(h+1e-6).
// We pre-scale y by c so the S reaching stage C is already c^2-scaled.
#define KSCALE 1.4426935981939225f

__device__ __forceinline__ float sqrt_abs_approx(float x) {
    float r;
    asm("sqrt.approx.f32 %0, %1;" : "=f"(r) : "f"(fabsf(x)));
    return r;
}
__device__ __forceinline__ float exp2_neg_approx(float x) {  // exp2(-x)
    float r;
    float nx = -x;
    asm("ex2.approx.f32 %0, %1;" : "=f"(r) : "f"(nx));
    return r;
}

// Vertical run start rows: 7 runs of length 5 covering rows 0..31 (overlaps
// write identical values -> benign).
__device__ __constant__ int c_i0[7] = {0, 5, 10, 15, 20, 24, 27};

__global__ __launch_bounds__(NTHREADS, 3)
void nlm_kernel(const float* __restrict__ rgb, float* __restrict__ out) {
    __shared__ float sy[SY_DIM * SY_STRIDE];
    __shared__ __half2 srg[SRGB_DIM * SRGB_STRIDE];  // (r,g) packed fp16x2
    __shared__ float sb[SRGB_DIM * SRGB_STRIDE];     // b exact fp32
    __shared__ __align__(16) float cs[2][TILE * CS_STRIDE];  // double-buffered

    const int tid = threadIdx.x;
    const int b   = blockIdx.z;
    const int ty0 = blockIdx.y * TILE;
    const int tx0 = blockIdx.x * TILE;

    const float* base = rgb + (size_t)b * 3 * HW;

    // ---- Fill luminance tile (halo 7) ----
    for (int idx = tid; idx < N_SY; idx += NTHREADS) {
        int r = idx / SY_DIM, c = idx - r * SY_DIM;
        int gy = (ty0 + r - HALO_Y) & (HH - 1);
        int gx = (tx0 + c - HALO_Y) & (WW - 1);
        size_t o = (size_t)gy * WW + gx;
        sy[r * SY_STRIDE + c] =
            (base[o] + base[o + HW] + base[o + 2 * HW]) * (1.0f / 3.0f);
    }

    // ---- Fill rgb tiles (halo 5): (r,g) as half2, b as fp32 ----
    for (int idx = tid; idx < N_SRGB; idx += NTHREADS) {
        int r = idx / SRGB_DIM, c = idx - r * SRGB_DIM;
        int gy = (ty0 + r - HALO_RGB) & (HH - 1);
        int gx = (tx0 + c - HALO_RGB) & (WW - 1);
        size_t o = (size_t)gy * WW + gx;
        int so = r * SRGB_STRIDE + c;
        srg[so] = __floats2half2_rn(base[o], base[o + HW]);
        sb[so]  = base[o + 2 * HW];
    }
    __syncthreads();

    // ---- Stage-AB task: vertical run of 5 cs outputs in one column ----
    const int tk   = (tid < N_CS_TASKS) ? tid : 0;
    const int col  = tk % CS_COLS;           // cs column (image col = col-2)
    const int run  = tk / CS_COLS;
    const int i0   = c_i0[run];

    // Center-y values (pre-scaled by KSCALE) — FIXED across all shifts.
    float yc[9];
#pragma unroll
    for (int u = 0; u < 9; u++)
        yc[u] = KSCALE * sy[(i0 + 5 + u) * SY_STRIDE + (col + 5)];

    // ---- Stage-C task: 4 consecutive output columns in one row ----
    const int ci  = tid >> 3;        // output row 0..31
    const int cj0 = (tid & 7) * 4;   // output col start

    float accR[4] = {0.f, 0.f, 0.f, 0.f};
    float accG[4] = {0.f, 0.f, 0.f, 0.f};
    float accB[4] = {0.f, 0.f, 0.f, 0.f};
    float wsum[4] = {0.f, 0.f, 0.f, 0.f};

    int buf = 0;
#pragma unroll 1
    for (int dx = -5; dx <= 5; dx++) {
        // Shifted-y column pointer for this dx (fixed within the dy loop).
        const float* ycol = &sy[col + 5 - dx];

        // Preload the 9-row shifted-y window (scaled) for dy = -5:
        float ysh[9];
#pragma unroll
        for (int u = 0; u < 9; u++)
            ysh[u] = KSCALE * ycol[(i0 + 10 + u) * SY_STRIDE];

#pragma unroll
        for (int dy = -5; dy <= 5; dy++) {
            // ---- Stage AB: fused d2 + vertical 5-sum -> cs[buf] ----
            if (tid < N_CS_TASKS) {
                float d[9];
#pragma unroll
                for (int u = 0; u < 9; u++) {
                    float dd = yc[u] - ysh[u];
                    d[u] = dd * dd;
                }
                float s = ((d[0] + d[1]) + (d[2] + d[3])) + d[4];
                float* cp = &cs[buf][i0 * CS_STRIDE + col];
                cp[0 * CS_STRIDE] = s;
#pragma unroll
                for (int v = 1; v < 5; v++) {
                    s += d[v + 4] - d[v - 1];
                    cp[v * CS_STRIDE] = s;
                }
            }
            __syncthreads();

            // ---- Stage C: horizontal sliding 5-sum + weight + accumulate ----
            const float4* cq =
                (const float4*)&cs[buf][ci * CS_STRIDE + cj0];
            float4 v0 = cq[0];
            float4 v1 = cq[1];

            float S0 = ((v0.x + v0.y) + (v0.z + v0.w)) + v1.x;
            float S1 = S0 + (v1.y - v0.x);
            float S2 = S1 + (v1.z - v0.y);
            float S3 = S2 + (v1.w - v0.z);

            const int sobase =
                (ci - dy + HALO_RGB) * SRGB_STRIDE + (cj0 - dx + HALO_RGB);
            float S[4] = {S0, S1, S2, S3};
#pragma unroll
            for (int m = 0; m < 4; m++) {
                float sq = sqrt_abs_approx(S[m]);   // = sqrt(c^2 * S)
                float w  = exp2_neg_approx(sq);     // = exp(-sqrt(S)/h')
                int so = sobase + m;
                float2 rg = __half22float2(srg[so]);
                accR[m] = fmaf(rg.x, w, accR[m]);
                accG[m] = fmaf(rg.y, w, accG[m]);
                accB[m] = fmaf(sb[so], w, accB[m]);
                wsum[m] += w;
            }
            buf ^= 1;
            // cs is double-buffered; the barrier above orders this
            // iteration's reads against writes two iterations out.

            // ---- Slide the shifted-y window down one row (for dy+1) ----
            if (dy < 5) {
#pragma unroll
                for (int u = 8; u >= 1; u--) ysh[u] = ysh[u - 1];
                ysh[0] = KSCALE * ycol[(i0 + 4 - dy) * SY_STRIDE];
            }
        }
    }

    // ---- Write out: out = acc / wsum, float4 per channel ----
    float* outb = out + (size_t)b * 3 * HW;
    size_t o = (size_t)(ty0 + ci) * WW + (tx0 + cj0);
    float inv0 = 1.0f / wsum[0], inv1 = 1.0f / wsum[1];
    float inv2 = 1.0f / wsum[2], inv3 = 1.0f / wsum[3];
    *(float4*)&outb[o] =
        make_float4(accR[0] * inv0, accR[1] * inv1, accR[2] * inv2, accR[3] * inv3);
    *(float4*)&outb[o + HW] =
        make_float4(accG[0] * inv0, accG[1] * inv1, accG[2] * inv2, accG[3] * inv3);
    *(float4*)&outb[o + 2 * HW] =
        make_float4(accB[0] * inv0, accB[1] * inv1, accB[2] * inv2, accB[3] * inv3);
}

extern "C" void kernel_launch(void* const* d_in, const int* in_sizes, int n_in,
                              void* d_out, int out_size) {
    const float* rgb = (const float*)d_in[0];
    float* out = (float*)d_out;
    dim3 grid(WW / TILE, HH / TILE, BATCH);
    nlm_kernel<<<grid, NTHREADS>>>(rgb, out);
}

// round 12
// speedup vs baseline: 1.0708x; 1.0708x over previous
#include <cuda_runtime.h>
#include <cuda_fp16.h>
#include <stdint.h>

// Problem constants (fixed shapes)
#define BATCH 8
#define HH 1024
#define WW 1024
#define HW (HH * WW)

#define TILE 32
#define NTHREADS 256

#define HALO_Y 7            // search radius 5 + patch radius 2
#define HALO_RGB 5
#define SY_DIM 46           // 32 + 2*7
#define SY_STRIDE 48
#define SRGB_DIM 42         // 32 + 2*5
#define SRGB_STRIDE 45      // odd -> conflict-free for stage-C pattern
#define CS_COLS 36          // columns j in [-2, 34)
#define CS_STRIDE 40        // multiple of 4 -> LDS.128-able in stage C

#define N_SY (SY_DIM * SY_DIM)
#define N_SRGB (SRGB_DIM * SRGB_DIM)
#define N_CS_TASKS 252      // 7 vertical runs x 36 columns

// w = exp(-sqrt(S)/(h+1e-6)) = exp2(-sqrt(c^2*S)), c = log2(e)/(h+1e-6).
// sy stores c * luminance, so S arrives pre-scaled by c^2.
#define KSCALE 1.4426935981939225f

// exp2(-sqrt(|x|)) with abs/neg folded into MUFU source modifiers.
__device__ __forceinline__ float weight_from_S(float x) {
    float w;
    asm("{\n\t"
        ".reg .f32 t;\n\t"
        "abs.f32 t, %1;\n\t"
        "sqrt.approx.f32 t, t;\n\t"
        "neg.f32 t, t;\n\t"
        "ex2.approx.f32 %0, t;\n\t"
        "}"
        : "=f"(w) : "f"(x));
    return w;
}

// Vertical run start rows: 7 runs of length 5 covering rows 0..31 (overlaps
// write identical values -> benign).
__device__ __constant__ int c_i0[7] = {0, 5, 10, 15, 20, 24, 27};

__global__ __launch_bounds__(NTHREADS, 3)
void nlm_kernel(const float* __restrict__ rgb, float* __restrict__ out) {
    __shared__ float sy[SY_DIM * SY_STRIDE];
    __shared__ __half2 srg[SRGB_DIM * SRGB_STRIDE];  // (r,g) packed fp16x2
    __shared__ float sb[SRGB_DIM * SRGB_STRIDE];     // b exact fp32
    __shared__ __align__(16) float cs[4][TILE * CS_STRIDE];  // 4-buffer rotation

    const int tid = threadIdx.x;
    const int b   = blockIdx.z;
    const int ty0 = blockIdx.y * TILE;
    const int tx0 = blockIdx.x * TILE;

    const float* base = rgb + (size_t)b * 3 * HW;

    // ---- Fill luminance tile (halo 7), pre-scaled by KSCALE ----
    for (int idx = tid; idx < N_SY; idx += NTHREADS) {
        int r = idx / SY_DIM, c = idx - r * SY_DIM;
        int gy = (ty0 + r - HALO_Y) & (HH - 1);
        int gx = (tx0 + c - HALO_Y) & (WW - 1);
        size_t o = (size_t)gy * WW + gx;
        sy[r * SY_STRIDE + c] =
            (base[o] + base[o + HW] + base[o + 2 * HW]) * (KSCALE / 3.0f);
    }

    // ---- Fill rgb tiles (halo 5): (r,g) as half2, b as fp32 ----
    for (int idx = tid; idx < N_SRGB; idx += NTHREADS) {
        int r = idx / SRGB_DIM, c = idx - r * SRGB_DIM;
        int gy = (ty0 + r - HALO_RGB) & (HH - 1);
        int gx = (tx0 + c - HALO_RGB) & (WW - 1);
        size_t o = (size_t)gy * WW + gx;
        int so = r * SRGB_STRIDE + c;
        srg[so] = __floats2half2_rn(base[o], base[o + HW]);
        sb[so]  = base[o + 2 * HW];
    }
    __syncthreads();

    // ---- Stage-AB task: vertical run of 5 cs outputs in one column ----
    const int tk   = (tid < N_CS_TASKS) ? tid : 0;
    const int col  = tk % CS_COLS;           // cs column (image col = col-2)
    const int run  = tk / CS_COLS;
    const int i0   = c_i0[run];

    // Center-y (already KSCALE-scaled) — FIXED across all shifts.
    float yc[9];
#pragma unroll
    for (int u = 0; u < 9; u++)
        yc[u] = sy[(i0 + 5 + u) * SY_STRIDE + (col + 5)];

    // ---- Stage-C task: 4 consecutive output columns in one row ----
    const int ci  = tid >> 3;        // output row 0..31
    const int cj0 = (tid & 7) * 4;   // output col start

    float accR[4] = {0.f, 0.f, 0.f, 0.f};
    float accG[4] = {0.f, 0.f, 0.f, 0.f};
    float accB[4] = {0.f, 0.f, 0.f, 0.f};
    float wsum[4] = {0.f, 0.f, 0.f, 0.f};

    // AB helper: 9 diffs vs window wptr[0..8], vertical sliding 5-sum -> buf
    auto stageAB = [&](float* bufp, const float* wptr) {
        float d[9];
#pragma unroll
        for (int u = 0; u < 9; u++) {
            float dd = yc[u] - wptr[u];
            d[u] = dd * dd;
        }
        float s = ((d[0] + d[1]) + (d[2] + d[3])) + d[4];
        float* cp = &bufp[i0 * CS_STRIDE + col];
        cp[0 * CS_STRIDE] = s;
#pragma unroll
        for (int v = 1; v < 5; v++) {
            s += d[v + 4] - d[v - 1];
            cp[v * CS_STRIDE] = s;
        }
    };

    // C helper: horizontal sliding 5-sum + weight + accumulate
    auto stageC = [&](const float* bufp, int dy, int dx) {
        const float4* cq = (const float4*)&bufp[ci * CS_STRIDE + cj0];
        float4 v0 = cq[0];
        float4 v1 = cq[1];

        float S0 = ((v0.x + v0.y) + (v0.z + v0.w)) + v1.x;
        float S1 = S0 + (v1.y - v0.x);
        float S2 = S1 + (v1.z - v0.y);
        float S3 = S2 + (v1.w - v0.z);

        const int sobase =
            (ci - dy + HALO_RGB) * SRGB_STRIDE + (cj0 - dx + HALO_RGB);
        float S[4] = {S0, S1, S2, S3};
#pragma unroll
        for (int m = 0; m < 4; m++) {
            float w = weight_from_S(S[m]);
            int so = sobase + m;
            float2 rg = __half22float2(srg[so]);
            accR[m] = fmaf(rg.x, w, accR[m]);
            accG[m] = fmaf(rg.y, w, accG[m]);
            accB[m] = fmaf(sb[so], w, accB[m]);
            wsum[m] += w;
        }
    };

#pragma unroll 1
    for (int dx = -5; dx <= 5; dx++) {
        // Shifted-y column pointer for this dx (fixed within the dy loop).
        const float* ycol = &sy[col + 5 - dx];

        // 10-row window w10[k] = row (i0 + 4 - dy) + k. Init for dy = -5:
        // rows i0+9 .. i0+18.
        float w10[10];
#pragma unroll
        for (int k = 0; k < 10; k++)
            w10[k] = ycol[(i0 + 9 + k) * SY_STRIDE];

        // 5 dy-pairs: (-5,-4), (-3,-2), (-1,0), (1,2), (3,4)
#pragma unroll
        for (int p = 0; p < 5; p++) {
            const int dy = -5 + 2 * p;
            const int bA = (p & 1) * 2;      // 0 or 2
            const int bB = bA + 1;           // 1 or 3

            if (tid < N_CS_TASKS) {
                stageAB(cs[bA], w10 + 1);    // dy   uses rows i0+5-dy ..
                stageAB(cs[bB], w10 + 0);    // dy+1 uses rows i0+4-dy ..
            }
            __syncthreads();

            stageC(cs[bA], dy, dx);
            stageC(cs[bB], dy + 1, dx);

            if (p < 4) {
                // slide window down 2 rows (toward dy+2)
#pragma unroll
                for (int k = 9; k >= 2; k--) w10[k] = w10[k - 2];
                w10[0] = ycol[(i0 + 2 - dy) * SY_STRIDE];
                w10[1] = ycol[(i0 + 3 - dy) * SY_STRIDE];
            } else {
                // slide by 1 for singleton dy = 5: rows i0 .. i0+9
#pragma unroll
                for (int k = 9; k >= 1; k--) w10[k] = w10[k - 1];
                w10[0] = ycol[i0 * SY_STRIDE];
            }
        }

        // Singleton dy = 5 (buffer 2: pair p=4 used buffers 0/1, and its
        // stage-C reads of buffers 2/3 from p=3 completed before the p=4
        // barrier).
        if (tid < N_CS_TASKS) stageAB(cs[2], w10 + 0);
        __syncthreads();
        stageC(cs[2], 5, dx);
    }

    // ---- Write out: out = acc / wsum, float4 per channel ----
    float* outb = out + (size_t)b * 3 * HW;
    size_t o = (size_t)(ty0 + ci) * WW + (tx0 + cj0);
    float inv0 = 1.0f / wsum[0], inv1 = 1.0f / wsum[1];
    float inv2 = 1.0f / wsum[2], inv3 = 1.0f / wsum[3];
    *(float4*)&outb[o] =
        make_float4(accR[0] * inv0, accR[1] * inv1, accR[2] * inv2, accR[3] * inv3);
    *(float4*)&outb[o + HW] =
        make_float4(accG[0] * inv0, accG[1] * inv1, accG[2] * inv2, accG[3] * inv3);
    *(float4*)&outb[o + 2 * HW] =
        make_float4(accB[0] * inv0, accB[1] * inv1, accB[2] * inv2, accB[3] * inv3);
}

extern "C" void kernel_launch(void* const* d_in, const int* in_sizes, int n_in,
                              void* d_out, int out_size) {
    const float* rgb = (const float*)d_in[0];
    float* out = (float*)d_out;
    dim3 grid(WW / TILE, HH / TILE, BATCH);
    nlm_kernel<<<grid, NTHREADS>>>(rgb, out);
}